// round 15
// baseline (speedup 1.0000x reference)
#include <cuda_runtime.h>
#include <cstdint>

#define BATCH 1024
#define NIN   2048
#define NOUT  2048
#define NC    10
#define TSTEPS 10

#define LDB      288                  // floats per kk-row of B stage (284 used + pad)
#define STAGE_A_F (16 * 128)          // 2048 floats = 8 KB
#define STAGE_B_F (16 * LDB)          // 4608 floats = 18 KB
#define STAGE_F   (STAGE_A_F + STAGE_B_F)
#define NSTG     4
#define SMEM_DYN (NSTG * STAGE_F * 4) // 106496 B
#define NCHUNKS  (STAGE_F / 4)        // 1664 16B chunks per stage

// ---------------------------------------------------------------------------
// Device scratch (no cudaMalloc allowed)
// ---------------------------------------------------------------------------
__device__ float g_At[BATCH * NIN];                 // 8 MB  A tiled: [mtile][it][kk][mm]
__device__ float g_Wd[16 * 128 * 16 * LDB];         // 37.7 MB B dup+staggered tiles
__device__ float g_h [BATCH * NOUT];                // 8 MB
__device__ float g_dec[TSTEPS * BATCH * NC];
__device__ float g_losspart[BATCH];

typedef unsigned long long u64t;

__device__ __forceinline__ void ffma2(u64t& acc, u64t a, u64t b) {
    asm("fma.rn.f32x2 %0, %1, %2, %0;" : "+l"(acc) : "l"(a), "l"(b));
}
__device__ __forceinline__ void unpack2(u64t v, float& lo, float& hi) {
    asm("mov.b64 {%0, %1}, %2;" : "=f"(lo), "=f"(hi) : "l"(v));
}
__device__ __forceinline__ uint32_t smem_u32(const void* p) {
    uint32_t a;
    asm("{ .reg .u64 t; cvta.to.shared.u64 t, %1; cvt.u32.u64 %0, t; }"
        : "=r"(a) : "l"(p));
    return a;
}
__device__ __forceinline__ void cp16(uint32_t dst, const void* src) {
    asm volatile("cp.async.cg.shared.global [%0], [%1], 16;" :: "r"(dst), "l"(src));
}
__device__ __forceinline__ void cp_commit() {
    asm volatile("cp.async.commit_group;");
}
template <int N>
__device__ __forceinline__ void cp_wait() {
    asm volatile("cp.async.wait_group %0;" :: "n"(N));
}

// b-group placement within a kk-row: group g (8 n-dup-pairs = 16 floats) at
// float offset 16*g + 4*(g>>1).  INJECTIVE (increments +16/+20, no overlap;
// max end = 268+16 = 284 <= LDB).  Bank-group residues (4g+(g>>1)) mod 8 =
// {0,4,1,5,2,6,3,7,4,0,5,1,6,2,7,3}: each 4-bank group serves exactly 2
// distinct addresses -> LDS.128 at the structural 2-phase floor.
__device__ __forceinline__ int bgrp(int g) { return 16 * g + 4 * (g >> 1); }

// ---------------------------------------------------------------------------
// Pre-kernel A: x[1024,2048] -> g_At[mtile(8)][it(128)][kk(16)][mm(128)]
// ---------------------------------------------------------------------------
__global__ __launch_bounds__(256)
void pre_a_kernel(const float* __restrict__ x)
{
    const int t  = blockIdx.x * 256 + threadIdx.x;   // 524288
    const int kc = t >> 10;                          // 0..511
    const int m  = t & 1023;

    const float4 v = ((const float4*)x)[(size_t)m * 512 + kc];
    const float vv[4] = {v.x, v.y, v.z, v.w};
    const int mtile = m >> 7, mm = m & 127;
    const int it = kc >> 2, kk0 = (kc & 3) * 4;
    float* dst = g_At + (((size_t)(mtile * 128 + it)) * 16 + kk0) * 128 + mm;
#pragma unroll
    for (int j = 0; j < 4; j++) dst[j * 128] = vv[j];
}

// ---------------------------------------------------------------------------
// Pre-kernel B: W[2048,2048] -> g_Wd[ntile(16)][it(128)][kk(16)][LDB]
// each value duplicated {b,b}, groups placed via bgrp.
// ---------------------------------------------------------------------------
__global__ __launch_bounds__(256)
void pre_b_kernel(const float* __restrict__ W)
{
    const int t  = blockIdx.x * 256 + threadIdx.x;   // 1048576
    const int kc = t >> 11;                          // 0..511
    const int n  = t & 2047;

    const float4 v = ((const float4*)W)[(size_t)n * 512 + kc];
    const float vv[4] = {v.x, v.y, v.z, v.w};
    const int ntile = n >> 7, nn = n & 127;
    const int it = kc >> 2, kk0 = (kc & 3) * 4;
    const int off = bgrp(nn >> 3) + 2 * (nn & 7);
    float* dst = g_Wd + (((size_t)(ntile * 128 + it)) * 16 + kk0) * LDB + off;
#pragma unroll
    for (int j = 0; j < 4; j++) {
        float2 d = make_float2(vv[j], vv[j]);
        *(float2*)(dst + (size_t)j * LDB) = d;
    }
}

// ---------------------------------------------------------------------------
// SGEMM (fp32 FFMA2, cp.async 4-stage, 512 threads, 4 warps/SMSP).
// Tile 128x128, thread = 4m x 8n, serial-K per thread (bit-identical order).
// ---------------------------------------------------------------------------
__global__ __launch_bounds__(512, 1)
void sgemm2_kernel()
{
    extern __shared__ float sm[];
    const uint32_t sbase = smem_u32(sm);

    const int tid = threadIdx.x;
    const int tx  = tid & 15;        // n group (8 cols)
    const int ty  = tid >> 4;        // m group (4 rows), 0..31
    const int ntile = blockIdx.x;    // 0..15
    const int mtile = blockIdx.y;    // 0..7

    const float* srcA0 = g_At + (size_t)mtile * 128 * 2048;         // per-it: +2048
    const float* srcB0 = g_Wd + (size_t)ntile * 128 * STAGE_B_F;    // per-it: +STAGE_B_F

    // stage loader: 1664 contiguous 16B chunks (A first, then B)
    auto load_stage = [&](int s, int itv) {
        const float* sA = srcA0 + (size_t)itv * STAGE_A_F;
        const float* sB = srcB0 + (size_t)itv * STAGE_B_F;
        const uint32_t db = sbase + s * (STAGE_F * 4);
#pragma unroll
        for (int c = tid; c < NCHUNKS; c += 512) {
            const float* src = (c < 512) ? (sA + c * 4) : (sB + (c - 512) * 4);
            cp16(db + c * 16, src);
        }
    };

    u64t acc[2][8];
#pragma unroll
    for (int i = 0; i < 2; i++)
#pragma unroll
        for (int j = 0; j < 8; j++) acc[i][j] = 0ull;

    // prologue: stages 0..2
    load_stage(0, 0); cp_commit();
    load_stage(1, 1); cp_commit();
    load_stage(2, 2); cp_commit();

    const int aoff = 4 * ty;             // floats within A kk-row
    const int boff = bgrp(tx);           // floats within B kk-row

    for (int it = 0; it < 128; it++) {
        cp_wait<2>();
        __syncthreads();

        if (it + 3 < 128) load_stage((it + 3) & 3, it + 3);
        cp_commit();

        const int p = it & 3;
        const float* stg = sm + p * STAGE_F;
#pragma unroll
        for (int kk = 0; kk < 16; kk++) {
            const u64t* ap = (const u64t*)(stg + kk * 128 + aoff);
            u64t a2[2];
            a2[0] = ap[0]; a2[1] = ap[1];
            const u64t* bp = (const u64t*)(stg + STAGE_A_F + kk * LDB + boff);
            u64t bd[8];
#pragma unroll
            for (int j = 0; j < 8; j++) bd[j] = bp[j];
#pragma unroll
            for (int i = 0; i < 2; i++)
#pragma unroll
                for (int j = 0; j < 8; j++)
                    ffma2(acc[i][j], a2[i], bd[j]);
        }
    }

    // epilogue: acc[i][j] lanes = rows (4ty+2i, 4ty+2i+1), col n0+8tx+j
    const int n0 = ntile * 128 + tx * 8;
#pragma unroll
    for (int i = 0; i < 2; i++) {
        float lo[8], hi[8];
#pragma unroll
        for (int j = 0; j < 8; j++) unpack2(acc[i][j], lo[j], hi[j]);
        const int row = mtile * 128 + 4 * ty + 2 * i;
        float* d0 = g_h + (size_t)row * NOUT + n0;
        float* d1 = d0 + NOUT;
        *(float4*)(d0)     = make_float4(lo[0], lo[1], lo[2], lo[3]);
        *(float4*)(d0 + 4) = make_float4(lo[4], lo[5], lo[6], lo[7]);
        *(float4*)(d1)     = make_float4(hi[0], hi[1], hi[2], hi[3]);
        *(float4*)(d1 + 4) = make_float4(hi[4], hi[5], hi[6], hi[7]);
    }
}

// ---------------------------------------------------------------------------
// LIF spike recurrence (elementwise, streaming).
// ---------------------------------------------------------------------------
__global__ __launch_bounds__(256)
void lif_kernel(float* __restrict__ out)
{
    const int idx = blockIdx.x * 256 + threadIdx.x;
    const int b = idx >> 8;
    const int n = (idx & 255) << 3;

    const float* hp = g_h + (size_t)b * NOUT + n;
    const float4 h0 = *(const float4*)(hp);
    const float4 h1 = *(const float4*)(hp + 4);
    const float h[8] = {h0.x, h0.y, h0.z, h0.w, h1.x, h1.y, h1.z, h1.w};

    float m[8], s[8];
#pragma unroll
    for (int j = 0; j < 8; j++) { m[j] = 0.0f; s[j] = 0.0f; }

#pragma unroll
    for (int t = 0; t < TSTEPS; t++) {
#pragma unroll
        for (int j = 0; j < 8; j++) {
            m[j] = m[j] * 0.2f + h[j] - s[j] * 0.1f;
            s[j] = (m[j] > 0.5f) ? 1.0f : 0.0f;
        }
        float* o = out + ((size_t)t * BATCH + b) * NOUT + n;
        *(float4*)(o)     = make_float4(s[0], s[1], s[2], s[3]);
        *(float4*)(o + 4) = make_float4(s[4], s[5], s[6], s[7]);
    }
}

// ---------------------------------------------------------------------------
// Decoder GEMV  g_dec[t][b][c] = spikes[t,b,:] . Wdec[c,:]
// ---------------------------------------------------------------------------
__global__ __launch_bounds__(256)
void dec_kernel(const float* __restrict__ spikes, const float* __restrict__ Wdec)
{
    const int gw = blockIdx.x * 8 + (threadIdx.x >> 5);
    const int lane = threadIdx.x & 31;
    const float* srow = spikes + (size_t)gw * NOUT;

    float acc[NC];
#pragma unroll
    for (int c = 0; c < NC; c++) acc[c] = 0.0f;

#pragma unroll
    for (int j = 0; j < 16; j++) {
        const int col = j * 128 + lane * 4;
        const float4 sv = *(const float4*)(srow + col);
#pragma unroll
        for (int c = 0; c < NC; c++) {
            const float4 w = *(const float4*)(Wdec + (size_t)c * NOUT + col);
            acc[c] = fmaf(sv.x, w.x,
                     fmaf(sv.y, w.y,
                     fmaf(sv.z, w.z,
                     fmaf(sv.w, w.w, acc[c]))));
        }
    }
#pragma unroll
    for (int c = 0; c < NC; c++) {
        float v = acc[c];
#pragma unroll
        for (int off = 16; off > 0; off >>= 1)
            v += __shfl_xor_sync(0xffffffffu, v, off);
        if (lane == 0) g_dec[(size_t)gw * NC + c] = v;
    }
}

// ---------------------------------------------------------------------------
// Loss partial + reduce.
// ---------------------------------------------------------------------------
__global__ __launch_bounds__(128)
void loss_kernel(const float* __restrict__ y1h)
{
    const int b = blockIdx.x * 128 + threadIdx.x;

    float ym[NC], ys[NC], yoh[NC];
#pragma unroll
    for (int c = 0; c < NC; c++) {
        ym[c] = 0.0f; ys[c] = 0.0f;
        yoh[c] = y1h[(size_t)b * NC + c];
    }
    float loss = 0.0f;
#pragma unroll
    for (int t = 0; t < TSTEPS; t++) {
#pragma unroll
        for (int c = 0; c < NC; c++) {
            const float d = g_dec[((size_t)t * BATCH + b) * NC + c];
            ym[c] = ym[c] * 0.2f + d - ys[c] * 0.1f;
            ys[c] = (ym[c] > 0.5f) ? 1.0f : 0.0f;
            const float e = ys[c] - yoh[c];
            loss = fmaf(e, e, loss);
        }
    }
    g_losspart[b] = loss;
}

__global__ void loss_reduce_kernel(float* __restrict__ out)
{
    __shared__ float sh[256];
    const int tid = threadIdx.x;
    float s = 0.0f;
    for (int i = tid; i < BATCH; i += 256) s += g_losspart[i];
    sh[tid] = s;
    __syncthreads();
    for (int off = 128; off > 0; off >>= 1) {
        if (tid < off) sh[tid] += sh[tid + off];
        __syncthreads();
    }
    if (tid == 0)
        out[(size_t)TSTEPS * BATCH * NOUT] = sh[0] / (float)(BATCH * NC);
}

// ---------------------------------------------------------------------------
// Launch
// ---------------------------------------------------------------------------
extern "C" void kernel_launch(void* const* d_in, const int* in_sizes, int n_in,
                              void* d_out, int out_size)
{
    const float* x    = (const float*)d_in[0];
    const float* Wenc = (const float*)d_in[1];
    const float* Wdec = (const float*)d_in[2];
    const float* y1h  = (const float*)d_in[3];
    float* out = (float*)d_out;

    cudaFuncSetAttribute(sgemm2_kernel,
                         cudaFuncAttributeMaxDynamicSharedMemorySize, SMEM_DYN);

    pre_a_kernel<<<2048, 256>>>(x);
    pre_b_kernel<<<4096, 256>>>(Wenc);
    sgemm2_kernel<<<dim3(16, 8), 512, SMEM_DYN>>>();
    lif_kernel<<<1024, 256>>>(out);
    dec_kernel<<<1280, 256>>>(out, Wdec);
    if (out_size > TSTEPS * BATCH * NOUT) {
        loss_kernel<<<8, 128>>>(y1h);
        loss_reduce_kernel<<<1, 256>>>(out);
    }
}